// round 1
// baseline (speedup 1.0000x reference)
#include <cuda_runtime.h>

#define BH 64
#define SS 8192
#define DD 64
#define SPLIT 16
#define CHUNK (SS/SPLIT)   // 512
#define CH 16              // s-rows per smem tile in pass1
#define TS 32              // s-rows per block in pass2

__device__ float g_kv_part[SPLIT][BH][DD*DD];
__device__ float g_ks_part[SPLIT][BH][DD];
__device__ float g_kv[BH][DD*DD];
__device__ float g_ks[BH][DD];

typedef unsigned long long u64;

__device__ __forceinline__ u64 pack2(float a, float b){
    u64 r; asm("mov.b64 %0, {%1,%2};" : "=l"(r) : "f"(a), "f"(b)); return r;
}
__device__ __forceinline__ void unpack2(u64 v, float &a, float &b){
    asm("mov.b64 {%0,%1}, %2;" : "=f"(a), "=f"(b) : "l"(v));
}
__device__ __forceinline__ u64 ffma2(u64 a, u64 b, u64 c){
    u64 d; asm("fma.rn.f32x2 %0, %1, %2, %3;" : "=l"(d) : "l"(a), "l"(b), "l"(c)); return d;
}

// Pass 1: per (split-chunk, bh) compute partial kv[64][64] = sum_s relu(k)[d] * v[e]
// and partial ksum[64] = sum_s relu(k)[d].
__global__ void __launch_bounds__(256) pass1_kernel(const float* __restrict__ K,
                                                    const float* __restrict__ V){
    __shared__ float sk2[CH][2*DD];   // k duplicated: sk2[ss][2d]=sk2[ss][2d+1]=relu(k[ss][d])
    __shared__ float sv [CH][DD];
    __shared__ float ksb[16][DD];
    int bh = blockIdx.y, ck = blockIdx.x;
    const float* Kp = K + ((size_t)bh*SS + (size_t)ck*CHUNK)*DD;
    const float* Vp = V + ((size_t)bh*SS + (size_t)ck*CHUNK)*DD;
    int tid = threadIdx.x;
    int tx = tid & 15, ty = tid >> 4;
    int lrow = tid >> 4;            // load row within CH x 64 tile
    int lcol = (tid & 15) * 4;      // load col
    u64 acc[4][2];
    #pragma unroll
    for(int i=0;i<4;i++){ acc[i][0]=0ULL; acc[i][1]=0ULL; }
    float ksl0=0.f, ksl1=0.f, ksl2=0.f, ksl3=0.f;

    for(int s0=0; s0<CHUNK; s0+=CH){
        float4 kq = ((const float4*)(Kp + (size_t)s0*DD))[tid];
        float4 vq = ((const float4*)(Vp + (size_t)s0*DD))[tid];
        kq.x=fmaxf(kq.x,0.f); kq.y=fmaxf(kq.y,0.f);
        kq.z=fmaxf(kq.z,0.f); kq.w=fmaxf(kq.w,0.f);
        ksl0+=kq.x; ksl1+=kq.y; ksl2+=kq.z; ksl3+=kq.w;
        __syncthreads();   // previous tile fully consumed
        float4* dst = (float4*)&sk2[lrow][2*lcol];
        dst[0] = make_float4(kq.x,kq.x,kq.y,kq.y);
        dst[1] = make_float4(kq.z,kq.z,kq.w,kq.w);
        *((float4*)&sv[lrow][lcol]) = vq;
        __syncthreads();
        #pragma unroll
        for(int ss=0; ss<CH; ss++){
            ulonglong2 vv  = *(const ulonglong2*)&sv [ss][tx*4];
            ulonglong2 k01 = *(const ulonglong2*)&sk2[ss][ty*8];
            ulonglong2 k23 = *(const ulonglong2*)&sk2[ss][ty*8+4];
            acc[0][0]=ffma2(k01.x, vv.x, acc[0][0]); acc[0][1]=ffma2(k01.x, vv.y, acc[0][1]);
            acc[1][0]=ffma2(k01.y, vv.x, acc[1][0]); acc[1][1]=ffma2(k01.y, vv.y, acc[1][1]);
            acc[2][0]=ffma2(k23.x, vv.x, acc[2][0]); acc[2][1]=ffma2(k23.x, vv.y, acc[2][1]);
            acc[3][0]=ffma2(k23.y, vv.x, acc[3][0]); acc[3][1]=ffma2(k23.y, vv.y, acc[3][1]);
        }
    }
    // store kv partial: thread covers d = ty*4..ty*4+3, e = tx*4..tx*4+3
    float* outp = g_kv_part[ck][bh];
    #pragma unroll
    for(int i=0;i<4;i++){
        float4 r;
        unpack2(acc[i][0], r.x, r.y);
        unpack2(acc[i][1], r.z, r.w);
        *((float4*)(outp + (ty*4+i)*DD + tx*4)) = r;
    }
    // ksum block reduce (16 row-groups -> 1)
    __syncthreads();
    ksb[lrow][lcol+0]=ksl0; ksb[lrow][lcol+1]=ksl1;
    ksb[lrow][lcol+2]=ksl2; ksb[lrow][lcol+3]=ksl3;
    __syncthreads();
    if(tid < DD){
        float s=0.f;
        #pragma unroll
        for(int r=0;r<16;r++) s += ksb[r][tid];
        g_ks_part[ck][bh][tid]=s;
    }
}

// Reduce the SPLIT partials -> g_kv, g_ks (deterministic, no atomics)
__global__ void __launch_bounds__(256) reduce_kernel(){
    int bh = blockIdx.x;
    int tid = threadIdx.x;
    #pragma unroll
    for(int i=0;i<4;i++){
        int idx = tid + i*256;            // 1024 float4 = 4096 floats
        float4 s = make_float4(0.f,0.f,0.f,0.f);
        #pragma unroll
        for(int c=0;c<SPLIT;c++){
            float4 p = ((const float4*)g_kv_part[c][bh])[idx];
            s.x+=p.x; s.y+=p.y; s.z+=p.z; s.w+=p.w;
        }
        ((float4*)g_kv[bh])[idx] = s;
    }
    if(tid < DD){
        float s=0.f;
        #pragma unroll
        for(int c=0;c<SPLIT;c++) s += g_ks_part[c][bh][tid];
        g_ks[bh][tid]=s;
    }
}

// Pass 2: out[s][e] = (sum_d relu(q)[s][d]*kv[d][e]) / max(sum_d relu(q)[s][d]*ks[d], 1e-6)
__global__ void __launch_bounds__(256) pass2_kernel(const float* __restrict__ Q,
                                                    float* __restrict__ O){
    __shared__ float skv[DD*DD];     // 16 KB, [d][e]
    __shared__ float sq [TS][DD];    // 8 KB, relu(q)
    __shared__ float sks[DD];
    __shared__ float snp[TS][16];
    int bh = blockIdx.y;
    int s0 = blockIdx.x * TS;
    int tid = threadIdx.x;
    const float* Qp = Q + ((size_t)bh*SS + s0)*DD;

    #pragma unroll
    for(int i=0;i<4;i++)
        ((float4*)skv)[tid + i*256] = ((const float4*)g_kv[bh])[tid + i*256];
    if(tid < DD) sks[tid] = g_ks[bh][tid];
    #pragma unroll
    for(int i=0;i<2;i++){
        float4 q = ((const float4*)Qp)[tid + i*256];
        q.x=fmaxf(q.x,0.f); q.y=fmaxf(q.y,0.f);
        q.z=fmaxf(q.z,0.f); q.w=fmaxf(q.w,0.f);
        ((float4*)sq)[tid + i*256] = q;
    }
    __syncthreads();

    int tx = tid & 15, rg = tid >> 4;
    int r0 = rg, r1 = rg + 16;
    u64 a00=0ULL, a01=0ULL, a10=0ULL, a11=0ULL;
    #pragma unroll
    for(int d=0; d<DD; d+=4){
        float4 q0 = *(const float4*)&sq[r0][d];
        float4 q1 = *(const float4*)&sq[r1][d];
        ulonglong2 kv0 = *(const ulonglong2*)&skv[(d+0)*DD + tx*4];
        ulonglong2 kv1 = *(const ulonglong2*)&skv[(d+1)*DD + tx*4];
        ulonglong2 kv2 = *(const ulonglong2*)&skv[(d+2)*DD + tx*4];
        ulonglong2 kv3 = *(const ulonglong2*)&skv[(d+3)*DD + tx*4];
        u64 p;
        p = pack2(q0.x,q0.x); a00=ffma2(p,kv0.x,a00); a01=ffma2(p,kv0.y,a01);
        p = pack2(q0.y,q0.y); a00=ffma2(p,kv1.x,a00); a01=ffma2(p,kv1.y,a01);
        p = pack2(q0.z,q0.z); a00=ffma2(p,kv2.x,a00); a01=ffma2(p,kv2.y,a01);
        p = pack2(q0.w,q0.w); a00=ffma2(p,kv3.x,a00); a01=ffma2(p,kv3.y,a01);
        p = pack2(q1.x,q1.x); a10=ffma2(p,kv0.x,a10); a11=ffma2(p,kv0.y,a11);
        p = pack2(q1.y,q1.y); a10=ffma2(p,kv1.x,a10); a11=ffma2(p,kv1.y,a11);
        p = pack2(q1.z,q1.z); a10=ffma2(p,kv2.x,a10); a11=ffma2(p,kv2.y,a11);
        p = pack2(q1.w,q1.w); a10=ffma2(p,kv3.x,a10); a11=ffma2(p,kv3.y,a11);
    }

    // per-row normalizer: each tx covers d in [tx*4, tx*4+4)
    float4 qa0 = *(const float4*)&sq[r0][tx*4];
    float4 qa1 = *(const float4*)&sq[r1][tx*4];
    float4 ks4 = *(const float4*)&sks[tx*4];
    float n0 = qa0.x*ks4.x + qa0.y*ks4.y + qa0.z*ks4.z + qa0.w*ks4.w;
    float n1 = qa1.x*ks4.x + qa1.y*ks4.y + qa1.z*ks4.z + qa1.w*ks4.w;
    snp[r0][tx]=n0; snp[r1][tx]=n1;
    __syncthreads();
    float t0=0.f, t1=0.f;
    #pragma unroll
    for(int j=0;j<16;j++){ t0+=snp[r0][j]; t1+=snp[r1][j]; }
    float inv0 = 1.0f / fmaxf(t0, 1e-6f);
    float inv1 = 1.0f / fmaxf(t1, 1e-6f);

    float4 o0, o1;
    unpack2(a00,o0.x,o0.y); unpack2(a01,o0.z,o0.w);
    unpack2(a10,o1.x,o1.y); unpack2(a11,o1.z,o1.w);
    o0.x*=inv0; o0.y*=inv0; o0.z*=inv0; o0.w*=inv0;
    o1.x*=inv1; o1.y*=inv1; o1.z*=inv1; o1.w*=inv1;
    *((float4*)(O + ((size_t)bh*SS + s0 + r0)*DD + tx*4)) = o0;
    *((float4*)(O + ((size_t)bh*SS + s0 + r1)*DD + tx*4)) = o1;
}

extern "C" void kernel_launch(void* const* d_in, const int* in_sizes, int n_in,
                              void* d_out, int out_size){
    const float* Q = (const float*)d_in[0];
    const float* K = (const float*)d_in[1];
    const float* V = (const float*)d_in[2];
    float* O = (float*)d_out;
    pass1_kernel<<<dim3(SPLIT, BH), 256>>>(K, V);
    reduce_kernel<<<BH, 256>>>();
    pass2_kernel<<<dim3(SS/TS, BH), 256>>>(Q, O);
}

// round 2
// speedup vs baseline: 1.2007x; 1.2007x over previous
#include <cuda_runtime.h>

#define BH 64
#define SS 8192
#define DD 64
#define SPLIT 16
#define CHUNK (SS/SPLIT)     // 512
#define CH1 16               // pass1 smem tile rows
#define NT1 (CHUNK/CH1)      // 32
#define TS2 32               // pass2 smem tile rows
#define NT2 (CHUNK/TS2)      // 16
#define QPAD 68              // pass2 q row pad (floats), 272B: 16B aligned, 2-way bank worst

__device__ float g_kv_part[SPLIT][BH][DD*DD];
__device__ float g_ks_part[SPLIT][BH][DD];
__device__ float g_kv[BH][DD*DD];
__device__ float g_ks[BH][DD];

typedef unsigned long long u64;

__device__ __forceinline__ u64 pack2(float a, float b){
    u64 r; asm("mov.b64 %0, {%1,%2};" : "=l"(r) : "f"(a), "f"(b)); return r;
}
__device__ __forceinline__ void unpack2(u64 v, float &a, float &b){
    asm("mov.b64 {%0,%1}, %2;" : "=f"(a), "=f"(b) : "l"(v));
}
__device__ __forceinline__ u64 ffma2(u64 a, u64 b, u64 c){
    u64 d; asm("fma.rn.f32x2 %0, %1, %2, %3;" : "=l"(d) : "l"(a), "l"(b), "l"(c)); return d;
}
__device__ __forceinline__ unsigned smem_u32(const void* p){
    return (unsigned)__cvta_generic_to_shared(p);
}
#define CP_ASYNC16(dst,src) asm volatile("cp.async.ca.shared.global [%0],[%1],16;\n"::"r"(dst),"l"(src))
#define CP_COMMIT()  asm volatile("cp.async.commit_group;\n")
#define CP_WAIT(n)   asm volatile("cp.async.wait_group %0;\n"::"n"(n))

// ---------------------------------------------------------------------------
// Pass 1: kv_part[d][e] = sum_s relu(k[s][d]) * v[s][e], ks_part[d] = sum relu(k)
// 64 threads/block, thread tile 8d x 8e.
// ---------------------------------------------------------------------------
__global__ void __launch_bounds__(64, 8) pass1_kernel(const float* __restrict__ K,
                                                      const float* __restrict__ V){
    __shared__ float sk[2][CH1][DD];
    __shared__ float sv[2][CH1][DD];
    __shared__ float ksb[4][DD];

    const int bh = blockIdx.y, ck = blockIdx.x;
    const float4* Kp = (const float4*)(K + ((size_t)bh*SS + (size_t)ck*CHUNK)*DD);
    const float4* Vp = (const float4*)(V + ((size_t)bh*SS + (size_t)ck*CHUNK)*DD);
    const int tid = threadIdx.x;
    const int tx = tid & 7, ty = tid >> 3;      // compute: e-group, d-group
    const int lc = tid & 15, lr = tid >> 4;     // load: f4-col, row base

    u64 acc[8][4];
    #pragma unroll
    for(int i=0;i<8;i++){ acc[i][0]=0ULL; acc[i][1]=0ULL; acc[i][2]=0ULL; acc[i][3]=0ULL; }
    float4 ks4 = make_float4(0.f,0.f,0.f,0.f);

    float4 kst[4], vst[4];
    // prologue: load tile 0 into registers
    #pragma unroll
    for(int j=0;j<4;j++){
        int idx = (lr + 4*j)*16 + lc;
        kst[j] = Kp[idx];
        vst[j] = Vp[idx];
    }

    int buf = 0;
    for(int t=0; t<NT1; t++){
        __syncthreads();  // everyone done reading sk[buf]/sv[buf] (from iter t-2)
        // relu + ksum + store staged tile t into smem[buf]
        #pragma unroll
        for(int j=0;j<4;j++){
            float4 k = kst[j];
            k.x=fmaxf(k.x,0.f); k.y=fmaxf(k.y,0.f); k.z=fmaxf(k.z,0.f); k.w=fmaxf(k.w,0.f);
            ks4.x+=k.x; ks4.y+=k.y; ks4.z+=k.z; ks4.w+=k.w;
            int r = lr + 4*j;
            *((float4*)&sk[buf][r][lc*4]) = k;
            *((float4*)&sv[buf][r][lc*4]) = vst[j];
        }
        __syncthreads();
        // prefetch tile t+1
        if(t+1 < NT1){
            #pragma unroll
            for(int j=0;j<4;j++){
                int idx = ((t+1)*CH1 + lr + 4*j)*16 + lc;
                kst[j] = Kp[idx];
                vst[j] = Vp[idx];
            }
        }
        // compute tile t
        #pragma unroll
        for(int ss=0; ss<CH1; ss++){
            const float* kp = &sk[buf][ss][ty*8];
            float4 ka = *(const float4*)kp;
            float4 kb = *(const float4*)(kp+4);
            const float* vp = &sv[buf][ss][tx*8];
            ulonglong2 v0 = *(const ulonglong2*)vp;
            ulonglong2 v1 = *(const ulonglong2*)(vp+4);
            u64 b;
            b=pack2(ka.x,ka.x); acc[0][0]=ffma2(b,v0.x,acc[0][0]); acc[0][1]=ffma2(b,v0.y,acc[0][1]); acc[0][2]=ffma2(b,v1.x,acc[0][2]); acc[0][3]=ffma2(b,v1.y,acc[0][3]);
            b=pack2(ka.y,ka.y); acc[1][0]=ffma2(b,v0.x,acc[1][0]); acc[1][1]=ffma2(b,v0.y,acc[1][1]); acc[1][2]=ffma2(b,v1.x,acc[1][2]); acc[1][3]=ffma2(b,v1.y,acc[1][3]);
            b=pack2(ka.z,ka.z); acc[2][0]=ffma2(b,v0.x,acc[2][0]); acc[2][1]=ffma2(b,v0.y,acc[2][1]); acc[2][2]=ffma2(b,v1.x,acc[2][2]); acc[2][3]=ffma2(b,v1.y,acc[2][3]);
            b=pack2(ka.w,ka.w); acc[3][0]=ffma2(b,v0.x,acc[3][0]); acc[3][1]=ffma2(b,v0.y,acc[3][1]); acc[3][2]=ffma2(b,v1.x,acc[3][2]); acc[3][3]=ffma2(b,v1.y,acc[3][3]);
            b=pack2(kb.x,kb.x); acc[4][0]=ffma2(b,v0.x,acc[4][0]); acc[4][1]=ffma2(b,v0.y,acc[4][1]); acc[4][2]=ffma2(b,v1.x,acc[4][2]); acc[4][3]=ffma2(b,v1.y,acc[4][3]);
            b=pack2(kb.y,kb.y); acc[5][0]=ffma2(b,v0.x,acc[5][0]); acc[5][1]=ffma2(b,v0.y,acc[5][1]); acc[5][2]=ffma2(b,v1.x,acc[5][2]); acc[5][3]=ffma2(b,v1.y,acc[5][3]);
            b=pack2(kb.z,kb.z); acc[6][0]=ffma2(b,v0.x,acc[6][0]); acc[6][1]=ffma2(b,v0.y,acc[6][1]); acc[6][2]=ffma2(b,v1.x,acc[6][2]); acc[6][3]=ffma2(b,v1.y,acc[6][3]);
            b=pack2(kb.w,kb.w); acc[7][0]=ffma2(b,v0.x,acc[7][0]); acc[7][1]=ffma2(b,v0.y,acc[7][1]); acc[7][2]=ffma2(b,v1.x,acc[7][2]); acc[7][3]=ffma2(b,v1.y,acc[7][3]);
        }
        buf ^= 1;
    }

    // store kv partial tile
    float* outp = g_kv_part[ck][bh];
    #pragma unroll
    for(int i=0;i<8;i++){
        int d = ty*8 + i;
        float4 r0, r1;
        unpack2(acc[i][0], r0.x, r0.y); unpack2(acc[i][1], r0.z, r0.w);
        unpack2(acc[i][2], r1.x, r1.y); unpack2(acc[i][3], r1.z, r1.w);
        *((float4*)(outp + d*DD + tx*8))     = r0;
        *((float4*)(outp + d*DD + tx*8 + 4)) = r1;
    }
    // ksum reduce 4 row-groups -> 1
    __syncthreads();
    *((float4*)&ksb[lr][lc*4]) = ks4;
    __syncthreads();
    if(tid < DD){
        g_ks_part[ck][bh][tid] = ksb[0][tid]+ksb[1][tid]+ksb[2][tid]+ksb[3][tid];
    }
}

// ---------------------------------------------------------------------------
// Reduce SPLIT partials
// ---------------------------------------------------------------------------
__global__ void __launch_bounds__(256) reduce_kernel(){
    int bh = blockIdx.x;
    int tid = threadIdx.x;
    #pragma unroll
    for(int i=0;i<4;i++){
        int idx = tid + i*256;
        float4 s = make_float4(0.f,0.f,0.f,0.f);
        #pragma unroll
        for(int c=0;c<SPLIT;c++){
            float4 p = ((const float4*)g_kv_part[c][bh])[idx];
            s.x+=p.x; s.y+=p.y; s.z+=p.z; s.w+=p.w;
        }
        ((float4*)g_kv[bh])[idx] = s;
    }
    if(tid < DD){
        float s=0.f;
        #pragma unroll
        for(int c=0;c<SPLIT;c++) s += g_ks_part[c][bh][tid];
        g_ks[bh][tid]=s;
    }
}

// ---------------------------------------------------------------------------
// Pass 2: out[s][e] = (sum_d relu(q)*kv[d][e]) / max(sum_d relu(q)*ks[d],1e-6)
// 64 threads/block, thread tile 4s x 8e, Q streamed via cp.async.
// ---------------------------------------------------------------------------
__global__ void __launch_bounds__(64, 6) pass2_kernel(const float* __restrict__ Q,
                                                      float* __restrict__ O){
    __shared__ float skv[DD*DD];          // [d][e]
    __shared__ float sks[DD];
    __shared__ float sq[2][TS2][QPAD];

    const int bh = blockIdx.y;
    const int chunk = blockIdx.x;
    const size_t sbase = (size_t)bh*SS + (size_t)chunk*CHUNK;
    const float* Qp = Q + sbase*DD;
    float* Op = O + sbase*DD;
    const int tid = threadIdx.x;
    const int tx = tid & 7, ty = tid >> 3;    // e-group, s-group
    const int lc = tid & 15, lr = tid >> 4;   // load map
    const int ty4 = ty*4, tx8 = tx*8;

    // load kv + ks tiles
    #pragma unroll
    for(int i=0;i<16;i++)
        ((float4*)skv)[tid + i*64] = ((const float4*)g_kv[bh])[tid + i*64];
    sks[tid] = g_ks[bh][tid];   // tid 0..63 == DD

    // prologue: async-load q tile 0
    #pragma unroll
    for(int j=0;j<8;j++){
        int r = lr + 4*j;
        unsigned dst = smem_u32(&sq[0][r][lc*4]);
        CP_ASYNC16(dst, Qp + (size_t)r*DD + lc*4);
    }
    CP_COMMIT();

    for(int t=0; t<NT2; t++){
        int buf = t & 1;
        if(t+1 < NT2){
            #pragma unroll
            for(int j=0;j<8;j++){
                int r = lr + 4*j;
                unsigned dst = smem_u32(&sq[buf^1][r][lc*4]);
                CP_ASYNC16(dst, Qp + (size_t)((t+1)*TS2 + r)*DD + lc*4);
            }
            CP_COMMIT();
            CP_WAIT(1);
        } else {
            CP_WAIT(0);
        }
        __syncthreads();   // tile t visible to all; also covers skv/sks on t==0

        u64 a0[4], a1[4], a2[4], a3[4], an0=0ULL, an1=0ULL;
        #pragma unroll
        for(int c=0;c<4;c++){ a0[c]=0ULL; a1[c]=0ULL; a2[c]=0ULL; a3[c]=0ULL; }

        #pragma unroll 8
        for(int d=0; d<DD; d++){
            float q0 = fmaxf(sq[buf][ty4+0][d], 0.f);
            float q1 = fmaxf(sq[buf][ty4+1][d], 0.f);
            float q2 = fmaxf(sq[buf][ty4+2][d], 0.f);
            float q3 = fmaxf(sq[buf][ty4+3][d], 0.f);
            const float* wp = &skv[d*DD + tx8];
            ulonglong2 w0 = *(const ulonglong2*)wp;
            ulonglong2 w1 = *(const ulonglong2*)(wp+4);
            float ks = sks[d];
            an0 = ffma2(pack2(q0,q1), pack2(ks,ks), an0);
            an1 = ffma2(pack2(q2,q3), pack2(ks,ks), an1);
            u64 b;
            b=pack2(q0,q0); a0[0]=ffma2(b,w0.x,a0[0]); a0[1]=ffma2(b,w0.y,a0[1]); a0[2]=ffma2(b,w1.x,a0[2]); a0[3]=ffma2(b,w1.y,a0[3]);
            b=pack2(q1,q1); a1[0]=ffma2(b,w0.x,a1[0]); a1[1]=ffma2(b,w0.y,a1[1]); a1[2]=ffma2(b,w1.x,a1[2]); a1[3]=ffma2(b,w1.y,a1[3]);
            b=pack2(q2,q2); a2[0]=ffma2(b,w0.x,a2[0]); a2[1]=ffma2(b,w0.y,a2[1]); a2[2]=ffma2(b,w1.x,a2[2]); a2[3]=ffma2(b,w1.y,a2[3]);
            b=pack2(q3,q3); a3[0]=ffma2(b,w0.x,a3[0]); a3[1]=ffma2(b,w0.y,a3[1]); a3[2]=ffma2(b,w1.x,a3[2]); a3[3]=ffma2(b,w1.y,a3[3]);
        }

        float n0,n1,n2,n3;
        unpack2(an0, n0, n1);
        unpack2(an1, n2, n3);
        float i0 = 1.0f / fmaxf(n0, 1e-6f);
        float i1 = 1.0f / fmaxf(n1, 1e-6f);
        float i2 = 1.0f / fmaxf(n2, 1e-6f);
        float i3 = 1.0f / fmaxf(n3, 1e-6f);

        float* ob = Op + (size_t)(t*TS2)*DD;
        {
            float4 r0,r1;
            unpack2(a0[0],r0.x,r0.y); unpack2(a0[1],r0.z,r0.w); unpack2(a0[2],r1.x,r1.y); unpack2(a0[3],r1.z,r1.w);
            r0.x*=i0;r0.y*=i0;r0.z*=i0;r0.w*=i0; r1.x*=i0;r1.y*=i0;r1.z*=i0;r1.w*=i0;
            *((float4*)(ob + (size_t)(ty4+0)*DD + tx8)) = r0; *((float4*)(ob + (size_t)(ty4+0)*DD + tx8+4)) = r1;
            unpack2(a1[0],r0.x,r0.y); unpack2(a1[1],r0.z,r0.w); unpack2(a1[2],r1.x,r1.y); unpack2(a1[3],r1.z,r1.w);
            r0.x*=i1;r0.y*=i1;r0.z*=i1;r0.w*=i1; r1.x*=i1;r1.y*=i1;r1.z*=i1;r1.w*=i1;
            *((float4*)(ob + (size_t)(ty4+1)*DD + tx8)) = r0; *((float4*)(ob + (size_t)(ty4+1)*DD + tx8+4)) = r1;
            unpack2(a2[0],r0.x,r0.y); unpack2(a2[1],r0.z,r0.w); unpack2(a2[2],r1.x,r1.y); unpack2(a2[3],r1.z,r1.w);
            r0.x*=i2;r0.y*=i2;r0.z*=i2;r0.w*=i2; r1.x*=i2;r1.y*=i2;r1.z*=i2;r1.w*=i2;
            *((float4*)(ob + (size_t)(ty4+2)*DD + tx8)) = r0; *((float4*)(ob + (size_t)(ty4+2)*DD + tx8+4)) = r1;
            unpack2(a3[0],r0.x,r0.y); unpack2(a3[1],r0.z,r0.w); unpack2(a3[2],r1.x,r1.y); unpack2(a3[3],r1.z,r1.w);
            r0.x*=i3;r0.y*=i3;r0.z*=i3;r0.w*=i3; r1.x*=i3;r1.y*=i3;r1.z*=i3;r1.w*=i3;
            *((float4*)(ob + (size_t)(ty4+3)*DD + tx8)) = r0; *((float4*)(ob + (size_t)(ty4+3)*DD + tx8+4)) = r1;
        }
        __syncthreads();   // tile t fully consumed before buf is refilled at t+2
    }
}

extern "C" void kernel_launch(void* const* d_in, const int* in_sizes, int n_in,
                              void* d_out, int out_size){
    const float* Q = (const float*)d_in[0];
    const float* K = (const float*)d_in[1];
    const float* V = (const float*)d_in[2];
    float* O = (float*)d_out;
    pass1_kernel<<<dim3(SPLIT, BH), 64>>>(K, V);
    reduce_kernel<<<BH, 256>>>();
    pass2_kernel<<<dim3(SPLIT, BH), 64>>>(Q, O);
}

// round 4
// speedup vs baseline: 1.8758x; 1.5622x over previous
#include <cuda_runtime.h>
#include <cstdint>

#define BH 64
#define SS 8192
#define DD 64
#define SPLIT 16
#define CHUNK (SS/SPLIT)     // 512
#define CH1 16               // pass1 smem tile rows
#define NT1 (CHUNK/CH1)      // 32

__device__ float g_kv_part[SPLIT][BH][DD*DD];
__device__ float g_ks_part[SPLIT][BH][DD];
__device__ float g_bT[BH][DD][DD];   // g_bT[e][d] = tf32(kv[d][e])
__device__ float g_ks2[BH][DD];      // ksum

typedef unsigned long long u64;

__device__ __forceinline__ u64 pack2(float a, float b){
    u64 r; asm("mov.b64 %0, {%1,%2};" : "=l"(r) : "f"(a), "f"(b)); return r;
}
__device__ __forceinline__ void unpack2(u64 v, float &a, float &b){
    asm("mov.b64 {%0,%1}, %2;" : "=f"(a), "=f"(b) : "l"(v));
}
__device__ __forceinline__ u64 ffma2(u64 a, u64 b, u64 c){
    u64 d; asm("fma.rn.f32x2 %0, %1, %2, %3;" : "=l"(d) : "l"(a), "l"(b), "l"(c)); return d;
}
__device__ __forceinline__ float to_tf32f(float f){
    uint32_t u; asm("cvt.rna.tf32.f32 %0, %1;" : "=r"(u) : "f"(f));
    return __uint_as_float(u);
}
__device__ __forceinline__ uint32_t relu_tf32(float f){
    uint32_t u; float r = fmaxf(f, 0.f);
    asm("cvt.rna.tf32.f32 %0, %1;" : "=r"(u) : "f"(r));
    return u;
}
__device__ __forceinline__ void mma_tf32(float c[4], uint32_t a0, uint32_t a1,
                                         uint32_t a2, uint32_t a3,
                                         uint32_t b0, uint32_t b1){
    asm volatile(
        "mma.sync.aligned.m16n8k8.row.col.f32.tf32.tf32.f32 "
        "{%0,%1,%2,%3}, {%4,%5,%6,%7}, {%8,%9}, {%0,%1,%2,%3};"
        : "+f"(c[0]), "+f"(c[1]), "+f"(c[2]), "+f"(c[3])
        : "r"(a0), "r"(a1), "r"(a2), "r"(a3), "r"(b0), "r"(b1));
}

// ---------------------------------------------------------------------------
// Pass 1 (fp32/FFMA2, unchanged): kv_part = phi_k^T * v, ks_part = sum(phi_k)
// ---------------------------------------------------------------------------
__global__ void __launch_bounds__(64, 8) pass1_kernel(const float* __restrict__ K,
                                                      const float* __restrict__ V){
    __shared__ float sk[2][CH1][DD];
    __shared__ float sv[2][CH1][DD];
    __shared__ float ksb[4][DD];

    const int bh = blockIdx.y, ck = blockIdx.x;
    const float4* Kp = (const float4*)(K + ((size_t)bh*SS + (size_t)ck*CHUNK)*DD);
    const float4* Vp = (const float4*)(V + ((size_t)bh*SS + (size_t)ck*CHUNK)*DD);
    const int tid = threadIdx.x;
    const int tx = tid & 7, ty = tid >> 3;
    const int lc = tid & 15, lr = tid >> 4;

    u64 acc[8][4];
    #pragma unroll
    for(int i=0;i<8;i++){ acc[i][0]=0ULL; acc[i][1]=0ULL; acc[i][2]=0ULL; acc[i][3]=0ULL; }
    float4 ks4 = make_float4(0.f,0.f,0.f,0.f);

    float4 kst[4], vst[4];
    #pragma unroll
    for(int j=0;j<4;j++){
        int idx = (lr + 4*j)*16 + lc;
        kst[j] = Kp[idx];
        vst[j] = Vp[idx];
    }

    int buf = 0;
    for(int t=0; t<NT1; t++){
        __syncthreads();
        #pragma unroll
        for(int j=0;j<4;j++){
            float4 k = kst[j];
            k.x=fmaxf(k.x,0.f); k.y=fmaxf(k.y,0.f); k.z=fmaxf(k.z,0.f); k.w=fmaxf(k.w,0.f);
            ks4.x+=k.x; ks4.y+=k.y; ks4.z+=k.z; ks4.w+=k.w;
            int r = lr + 4*j;
            *((float4*)&sk[buf][r][lc*4]) = k;
            *((float4*)&sv[buf][r][lc*4]) = vst[j];
        }
        __syncthreads();
        if(t+1 < NT1){
            #pragma unroll
            for(int j=0;j<4;j++){
                int idx = ((t+1)*CH1 + lr + 4*j)*16 + lc;
                kst[j] = Kp[idx];
                vst[j] = Vp[idx];
            }
        }
        #pragma unroll
        for(int ss=0; ss<CH1; ss++){
            const float* kp = &sk[buf][ss][ty*8];
            float4 ka = *(const float4*)kp;
            float4 kb = *(const float4*)(kp+4);
            const float* vp = &sv[buf][ss][tx*8];
            ulonglong2 v0 = *(const ulonglong2*)vp;
            ulonglong2 v1 = *(const ulonglong2*)(vp+4);
            u64 b;
            b=pack2(ka.x,ka.x); acc[0][0]=ffma2(b,v0.x,acc[0][0]); acc[0][1]=ffma2(b,v0.y,acc[0][1]); acc[0][2]=ffma2(b,v1.x,acc[0][2]); acc[0][3]=ffma2(b,v1.y,acc[0][3]);
            b=pack2(ka.y,ka.y); acc[1][0]=ffma2(b,v0.x,acc[1][0]); acc[1][1]=ffma2(b,v0.y,acc[1][1]); acc[1][2]=ffma2(b,v1.x,acc[1][2]); acc[1][3]=ffma2(b,v1.y,acc[1][3]);
            b=pack2(ka.z,ka.z); acc[2][0]=ffma2(b,v0.x,acc[2][0]); acc[2][1]=ffma2(b,v0.y,acc[2][1]); acc[2][2]=ffma2(b,v1.x,acc[2][2]); acc[2][3]=ffma2(b,v1.y,acc[2][3]);
            b=pack2(ka.w,ka.w); acc[3][0]=ffma2(b,v0.x,acc[3][0]); acc[3][1]=ffma2(b,v0.y,acc[3][1]); acc[3][2]=ffma2(b,v1.x,acc[3][2]); acc[3][3]=ffma2(b,v1.y,acc[3][3]);
            b=pack2(kb.x,kb.x); acc[4][0]=ffma2(b,v0.x,acc[4][0]); acc[4][1]=ffma2(b,v0.y,acc[4][1]); acc[4][2]=ffma2(b,v1.x,acc[4][2]); acc[4][3]=ffma2(b,v1.y,acc[4][3]);
            b=pack2(kb.y,kb.y); acc[5][0]=ffma2(b,v0.x,acc[5][0]); acc[5][1]=ffma2(b,v0.y,acc[5][1]); acc[5][2]=ffma2(b,v1.x,acc[5][2]); acc[5][3]=ffma2(b,v1.y,acc[5][3]);
            b=pack2(kb.z,kb.z); acc[6][0]=ffma2(b,v0.x,acc[6][0]); acc[6][1]=ffma2(b,v0.y,acc[6][1]); acc[6][2]=ffma2(b,v1.x,acc[6][2]); acc[6][3]=ffma2(b,v1.y,acc[6][3]);
            b=pack2(kb.w,kb.w); acc[7][0]=ffma2(b,v0.x,acc[7][0]); acc[7][1]=ffma2(b,v0.y,acc[7][1]); acc[7][2]=ffma2(b,v1.x,acc[7][2]); acc[7][3]=ffma2(b,v1.y,acc[7][3]);
        }
        buf ^= 1;
    }

    float* outp = g_kv_part[ck][bh];
    #pragma unroll
    for(int i=0;i<8;i++){
        int d = ty*8 + i;
        float4 r0, r1;
        unpack2(acc[i][0], r0.x, r0.y); unpack2(acc[i][1], r0.z, r0.w);
        unpack2(acc[i][2], r1.x, r1.y); unpack2(acc[i][3], r1.z, r1.w);
        *((float4*)(outp + d*DD + tx*8))     = r0;
        *((float4*)(outp + d*DD + tx*8 + 4)) = r1;
    }
    __syncthreads();
    *((float4*)&ksb[lr][lc*4]) = ks4;
    __syncthreads();
    if(tid < DD){
        g_ks_part[ck][bh][tid] = ksb[0][tid]+ksb[1][tid]+ksb[2][tid]+ksb[3][tid];
    }
}

// ---------------------------------------------------------------------------
// Reduce: sum partials -> g_bT[bh][e][d] = tf32(kv[d][e]), g_ks2 = ksum
// ---------------------------------------------------------------------------
__global__ void __launch_bounds__(256) reduce_kernel(){
    int bh = blockIdx.x;
    int tid = threadIdx.x;
    #pragma unroll
    for(int i=0;i<4;i++){
        int idx = tid + i*256;            // over 1024 float4 of kv[d][e]
        int d = idx >> 4;
        int e = (idx & 15) * 4;
        float4 s = make_float4(0.f,0.f,0.f,0.f);
        #pragma unroll
        for(int c=0;c<SPLIT;c++){
            float4 p = ((const float4*)g_kv_part[c][bh])[idx];
            s.x+=p.x; s.y+=p.y; s.z+=p.z; s.w+=p.w;
        }
        g_bT[bh][e+0][d] = to_tf32f(s.x);
        g_bT[bh][e+1][d] = to_tf32f(s.y);
        g_bT[bh][e+2][d] = to_tf32f(s.z);
        g_bT[bh][e+3][d] = to_tf32f(s.w);
    }
    if(tid < DD){
        float s=0.f;
        #pragma unroll
        for(int c=0;c<SPLIT;c++) s += g_ks_part[c][bh][tid];
        g_ks2[bh][tid] = s;
    }
}

// ---------------------------------------------------------------------------
// Pass 2 (tf32 mma.sync): out[s][e] = (phi_q @ kv)[s][e] / max(phi_q·ksum,1e-6)
// Each warp: 16-row m-tiles, B fragments register-resident, no smem/syncs.
// ---------------------------------------------------------------------------
#define P2_HALVES 2
#define ROWS_PER_WARP (SS / P2_HALVES / 8)    // 512
#define MT_PER_WARP (ROWS_PER_WARP / 16)      // 32

__global__ void __launch_bounds__(256, 1) pass2_kernel(const float* __restrict__ Q,
                                                       float* __restrict__ O){
    const int bh = blockIdx.y;
    const int half = blockIdx.x;
    const int tid = threadIdx.x;
    const int w = tid >> 5, lane = tid & 31;
    const int g = lane >> 2, tg = lane & 3;

    // B fragments: b0 = kv[k=s*8+tg][n=nt*8+g] = g_bT[n][k]
    uint32_t B0[8][8], B1[8][8];
    {
        const float* Bp = &g_bT[bh][0][0];
        #pragma unroll
        for(int n=0;n<8;n++){
            #pragma unroll
            for(int s=0;s<8;s++){
                B0[n][s] = __float_as_uint(Bp[(n*8+g)*DD + s*8+tg]);
                B1[n][s] = __float_as_uint(Bp[(n*8+g)*DD + s*8+tg+4]);
            }
        }
    }
    float ksA[8], ksB[8];
    #pragma unroll
    for(int s=0;s<8;s++){
        ksA[s] = g_ks2[bh][s*8+tg];
        ksB[s] = g_ks2[bh][s*8+tg+4];
    }

    const size_t rowbase = (size_t)bh*SS + (size_t)half*(SS/P2_HALVES) + (size_t)w*ROWS_PER_WARP;

    for(int mt=0; mt<MT_PER_WARP; mt++){
        const float* Ap = Q + (rowbase + (size_t)mt*16)*DD;
        float C[8][4];
        #pragma unroll
        for(int n=0;n<8;n++){ C[n][0]=0.f; C[n][1]=0.f; C[n][2]=0.f; C[n][3]=0.f; }
        float n0 = 0.f, n1 = 0.f;

        #pragma unroll
        for(int s=0;s<8;s++){
            uint32_t a0 = relu_tf32(Ap[(size_t)g*DD      + s*8+tg]);
            uint32_t a1 = relu_tf32(Ap[(size_t)(g+8)*DD  + s*8+tg]);
            uint32_t a2 = relu_tf32(Ap[(size_t)g*DD      + s*8+tg+4]);
            uint32_t a3 = relu_tf32(Ap[(size_t)(g+8)*DD  + s*8+tg+4]);
            n0 += __uint_as_float(a0)*ksA[s] + __uint_as_float(a2)*ksB[s];
            n1 += __uint_as_float(a1)*ksA[s] + __uint_as_float(a3)*ksB[s];
            #pragma unroll
            for(int n=0;n<8;n++)
                mma_tf32(C[n], a0, a1, a2, a3, B0[n][s], B1[n][s]);
        }

        // quad reduce (lanes sharing the same rows differ only in tg = lane bits 0..1)
        n0 += __shfl_xor_sync(0xffffffffu, n0, 1);
        n0 += __shfl_xor_sync(0xffffffffu, n0, 2);
        n1 += __shfl_xor_sync(0xffffffffu, n1, 1);
        n1 += __shfl_xor_sync(0xffffffffu, n1, 2);
        float i0 = 1.0f / fmaxf(n0, 1e-6f);
        float i1 = 1.0f / fmaxf(n1, 1e-6f);

        float* Or0 = O + (rowbase + (size_t)mt*16 + g)*DD;
        float* Or1 = Or0 + 8*DD;
        #pragma unroll
        for(int n=0;n<8;n++){
            float2 v0 = make_float2(C[n][0]*i0, C[n][1]*i0);
            float2 v1 = make_float2(C[n][2]*i1, C[n][3]*i1);
            *(float2*)(Or0 + n*8 + tg*2) = v0;
            *(float2*)(Or1 + n*8 + tg*2) = v1;
        }
    }
}

extern "C" void kernel_launch(void* const* d_in, const int* in_sizes, int n_in,
                              void* d_out, int out_size){
    const float* Q = (const float*)d_in[0];
    const float* K = (const float*)d_in[1];
    const float* V = (const float*)d_in[2];
    float* O = (float*)d_out;
    pass1_kernel<<<dim3(SPLIT, BH), 64>>>(K, V);
    reduce_kernel<<<BH, 256>>>();
    pass2_kernel<<<dim3(P2_HALVES, BH), 256>>>(Q, O);
}

// round 5
// speedup vs baseline: 2.2682x; 1.2092x over previous
#include <cuda_runtime.h>
#include <cstdint>

#define BH 64
#define SS 8192
#define DD 64
#define SPLIT 16

__device__ float g_kv_part[SPLIT][BH][DD*DD];
__device__ float g_ks_part[SPLIT][BH][DD];
__device__ float g_bT[BH][DD][DD];   // g_bT[e][d] = tf32(kv[d][e])
__device__ float g_ks2[BH][DD];      // ksum

__device__ __forceinline__ float to_tf32f(float f){
    uint32_t u; asm("cvt.rna.tf32.f32 %0, %1;" : "=r"(u) : "f"(f));
    return __uint_as_float(u);
}
__device__ __forceinline__ uint32_t cvt_tf32(float f){
    uint32_t u; asm("cvt.rna.tf32.f32 %0, %1;" : "=r"(u) : "f"(f));
    return u;
}
__device__ __forceinline__ uint32_t relu_tf32(float f){
    uint32_t u; float r = fmaxf(f, 0.f);
    asm("cvt.rna.tf32.f32 %0, %1;" : "=r"(u) : "f"(r));
    return u;
}
__device__ __forceinline__ void mma_tf32(float c[4], uint32_t a0, uint32_t a1,
                                         uint32_t a2, uint32_t a3,
                                         uint32_t b0, uint32_t b1){
    asm volatile(
        "mma.sync.aligned.m16n8k8.row.col.f32.tf32.tf32.f32 "
        "{%0,%1,%2,%3}, {%4,%5,%6,%7}, {%8,%9}, {%0,%1,%2,%3};"
        : "+f"(c[0]), "+f"(c[1]), "+f"(c[2]), "+f"(c[3])
        : "r"(a0), "r"(a1), "r"(a2), "r"(a3), "r"(b0), "r"(b1));
}

// ---------------------------------------------------------------------------
// Pass 1 (tf32 mma.sync): kv_part[d][e] = sum_s relu(k[s][d])*v[s][e]
// 8 warps/block, 2 blocks/bh; each warp owns 512 s-rows, C 64x64 in regs.
// ---------------------------------------------------------------------------
#define P1_BLOCKS 2
#define S_PER_WARP 512
#define KSTEPS (S_PER_WARP/8)   // 64

__global__ void __launch_bounds__(256, 1) pass1_kernel(const float* __restrict__ K,
                                                       const float* __restrict__ V){
    const int bh = blockIdx.y;
    const int tid = threadIdx.x;
    const int w = tid >> 5, lane = tid & 31;
    const int g = lane >> 2, tg = lane & 3;
    const int sp = blockIdx.x * 8 + w;           // 0..15 split index

    const float* Kp = K + ((size_t)bh*SS + (size_t)sp*S_PER_WARP)*DD;
    const float* Vp = V + ((size_t)bh*SS + (size_t)sp*S_PER_WARP)*DD;

    float C[4][8][4];
    #pragma unroll
    for(int mt=0;mt<4;mt++)
        #pragma unroll
        for(int nt=0;nt<8;nt++){ C[mt][nt][0]=0.f; C[mt][nt][1]=0.f; C[mt][nt][2]=0.f; C[mt][nt][3]=0.f; }
    float ksum[4][2];
    #pragma unroll
    for(int mt=0;mt<4;mt++){ ksum[mt][0]=0.f; ksum[mt][1]=0.f; }

    // raw staging registers (double buffered)
    float ra[16], rb[16], ra2[16], rb2[16];

    // load k-step 0
    #pragma unroll
    for(int mt=0;mt<4;mt++){
        int d0 = mt*16 + g;
        ra[mt*4+0] = Kp[(size_t)tg*DD + d0];
        ra[mt*4+1] = Kp[(size_t)tg*DD + d0 + 8];
        ra[mt*4+2] = Kp[(size_t)(tg+4)*DD + d0];
        ra[mt*4+3] = Kp[(size_t)(tg+4)*DD + d0 + 8];
    }
    #pragma unroll
    for(int nt=0;nt<8;nt++){
        rb[nt*2+0] = Vp[(size_t)tg*DD + nt*8 + g];
        rb[nt*2+1] = Vp[(size_t)(tg+4)*DD + nt*8 + g];
    }

    for(int ks=0; ks<KSTEPS; ks++){
        if(ks+1 < KSTEPS){
            const float* kb = Kp + (size_t)(ks+1)*8*DD;
            const float* vb = Vp + (size_t)(ks+1)*8*DD;
            #pragma unroll
            for(int mt=0;mt<4;mt++){
                int d0 = mt*16 + g;
                ra2[mt*4+0] = kb[(size_t)tg*DD + d0];
                ra2[mt*4+1] = kb[(size_t)tg*DD + d0 + 8];
                ra2[mt*4+2] = kb[(size_t)(tg+4)*DD + d0];
                ra2[mt*4+3] = kb[(size_t)(tg+4)*DD + d0 + 8];
            }
            #pragma unroll
            for(int nt=0;nt<8;nt++){
                rb2[nt*2+0] = vb[(size_t)tg*DD + nt*8 + g];
                rb2[nt*2+1] = vb[(size_t)(tg+4)*DD + nt*8 + g];
            }
        }
        // convert + mma current
        uint32_t A[4][4], B[8][2];
        #pragma unroll
        for(int mt=0;mt<4;mt++){
            A[mt][0] = relu_tf32(ra[mt*4+0]);
            A[mt][1] = relu_tf32(ra[mt*4+1]);
            A[mt][2] = relu_tf32(ra[mt*4+2]);
            A[mt][3] = relu_tf32(ra[mt*4+3]);
            ksum[mt][0] += __uint_as_float(A[mt][0]) + __uint_as_float(A[mt][2]);
            ksum[mt][1] += __uint_as_float(A[mt][1]) + __uint_as_float(A[mt][3]);
        }
        #pragma unroll
        for(int nt=0;nt<8;nt++){
            B[nt][0] = cvt_tf32(rb[nt*2+0]);
            B[nt][1] = cvt_tf32(rb[nt*2+1]);
        }
        #pragma unroll
        for(int mt=0;mt<4;mt++)
            #pragma unroll
            for(int nt=0;nt<8;nt++)
                mma_tf32(C[mt][nt], A[mt][0], A[mt][1], A[mt][2], A[mt][3],
                         B[nt][0], B[nt][1]);
        // rotate buffers
        #pragma unroll
        for(int i=0;i<16;i++){ ra[i]=ra2[i]; rb[i]=rb2[i]; }
    }

    // write kv partial: frag (mt,nt): rows mt*16+g / +8, cols nt*8 + 2*tg
    float* outp = g_kv_part[sp][bh];
    #pragma unroll
    for(int mt=0;mt<4;mt++){
        int r0 = mt*16 + g, r1 = r0 + 8;
        #pragma unroll
        for(int nt=0;nt<8;nt++){
            int col = nt*8 + tg*2;
            *(float2*)(outp + (size_t)r0*DD + col) = make_float2(C[mt][nt][0], C[mt][nt][1]);
            *(float2*)(outp + (size_t)r1*DD + col) = make_float2(C[mt][nt][2], C[mt][nt][3]);
        }
    }
    // ksum quad-reduce and write
    #pragma unroll
    for(int mt=0;mt<4;mt++){
        #pragma unroll
        for(int r=0;r<2;r++){
            float s = ksum[mt][r];
            s += __shfl_xor_sync(0xffffffffu, s, 1);
            s += __shfl_xor_sync(0xffffffffu, s, 2);
            ksum[mt][r] = s;
        }
    }
    if(tg == 0){
        #pragma unroll
        for(int mt=0;mt<4;mt++){
            g_ks_part[sp][bh][mt*16 + g]     = ksum[mt][0];
            g_ks_part[sp][bh][mt*16 + g + 8] = ksum[mt][1];
        }
    }
}

// ---------------------------------------------------------------------------
// Reduce: sum partials -> g_bT[bh][e][d] = tf32(kv[d][e]), g_ks2 = ksum
// ---------------------------------------------------------------------------
__global__ void __launch_bounds__(256) reduce_kernel(){
    int bh = blockIdx.x;
    int tid = threadIdx.x;
    #pragma unroll
    for(int i=0;i<4;i++){
        int idx = tid + i*256;            // over 1024 float4 of kv[d][e]
        int d = idx >> 4;
        int e = (idx & 15) * 4;
        float4 s = make_float4(0.f,0.f,0.f,0.f);
        #pragma unroll
        for(int c=0;c<SPLIT;c++){
            float4 p = ((const float4*)g_kv_part[c][bh])[idx];
            s.x+=p.x; s.y+=p.y; s.z+=p.z; s.w+=p.w;
        }
        g_bT[bh][e+0][d] = to_tf32f(s.x);
        g_bT[bh][e+1][d] = to_tf32f(s.y);
        g_bT[bh][e+2][d] = to_tf32f(s.z);
        g_bT[bh][e+3][d] = to_tf32f(s.w);
    }
    if(tid < DD){
        float s=0.f;
        #pragma unroll
        for(int c=0;c<SPLIT;c++) s += g_ks_part[c][bh][tid];
        g_ks2[bh][tid] = s;
    }
}

// ---------------------------------------------------------------------------
// Pass 2 (tf32 mma.sync): out[s][e] = (phi_q @ kv)[s][e] / max(phi_q·ksum,1e-6)
// ---------------------------------------------------------------------------
#define P2_HALVES 2
#define ROWS_PER_WARP (SS / P2_HALVES / 8)    // 512
#define MT_PER_WARP (ROWS_PER_WARP / 16)      // 32

__global__ void __launch_bounds__(256, 1) pass2_kernel(const float* __restrict__ Q,
                                                       float* __restrict__ O){
    const int bh = blockIdx.y;
    const int half = blockIdx.x;
    const int tid = threadIdx.x;
    const int w = tid >> 5, lane = tid & 31;
    const int g = lane >> 2, tg = lane & 3;

    uint32_t B0[8][8], B1[8][8];
    {
        const float* Bp = &g_bT[bh][0][0];
        #pragma unroll
        for(int n=0;n<8;n++){
            #pragma unroll
            for(int s=0;s<8;s++){
                B0[n][s] = __float_as_uint(Bp[(n*8+g)*DD + s*8+tg]);
                B1[n][s] = __float_as_uint(Bp[(n*8+g)*DD + s*8+tg+4]);
            }
        }
    }
    float ksA[8], ksB[8];
    #pragma unroll
    for(int s=0;s<8;s++){
        ksA[s] = g_ks2[bh][s*8+tg];
        ksB[s] = g_ks2[bh][s*8+tg+4];
    }

    const size_t rowbase = (size_t)bh*SS + (size_t)half*(SS/P2_HALVES) + (size_t)w*ROWS_PER_WARP;

    for(int mt=0; mt<MT_PER_WARP; mt++){
        const float* Ap = Q + (rowbase + (size_t)mt*16)*DD;
        float C[8][4];
        #pragma unroll
        for(int n=0;n<8;n++){ C[n][0]=0.f; C[n][1]=0.f; C[n][2]=0.f; C[n][3]=0.f; }
        float n0 = 0.f, n1 = 0.f;

        #pragma unroll
        for(int s=0;s<8;s++){
            uint32_t a0 = relu_tf32(Ap[(size_t)g*DD      + s*8+tg]);
            uint32_t a1 = relu_tf32(Ap[(size_t)(g+8)*DD  + s*8+tg]);
            uint32_t a2 = relu_tf32(Ap[(size_t)g*DD      + s*8+tg+4]);
            uint32_t a3 = relu_tf32(Ap[(size_t)(g+8)*DD  + s*8+tg+4]);
            n0 += __uint_as_float(a0)*ksA[s] + __uint_as_float(a2)*ksB[s];
            n1 += __uint_as_float(a1)*ksA[s] + __uint_as_float(a3)*ksB[s];
            #pragma unroll
            for(int n=0;n<8;n++)
                mma_tf32(C[n], a0, a1, a2, a3, B0[n][s], B1[n][s]);
        }

        n0 += __shfl_xor_sync(0xffffffffu, n0, 1);
        n0 += __shfl_xor_sync(0xffffffffu, n0, 2);
        n1 += __shfl_xor_sync(0xffffffffu, n1, 1);
        n1 += __shfl_xor_sync(0xffffffffu, n1, 2);
        float i0 = 1.0f / fmaxf(n0, 1e-6f);
        float i1 = 1.0f / fmaxf(n1, 1e-6f);

        float* Or0 = O + (rowbase + (size_t)mt*16 + g)*DD;
        float* Or1 = Or0 + 8*DD;
        #pragma unroll
        for(int n=0;n<8;n++){
            float2 v0 = make_float2(C[n][0]*i0, C[n][1]*i0);
            float2 v1 = make_float2(C[n][2]*i1, C[n][3]*i1);
            *(float2*)(Or0 + n*8 + tg*2) = v0;
            *(float2*)(Or1 + n*8 + tg*2) = v1;
        }
    }
}

extern "C" void kernel_launch(void* const* d_in, const int* in_sizes, int n_in,
                              void* d_out, int out_size){
    const float* Q = (const float*)d_in[0];
    const float* K = (const float*)d_in[1];
    const float* V = (const float*)d_in[2];
    float* O = (float*)d_out;
    pass1_kernel<<<dim3(P1_BLOCKS, BH), 256>>>(K, V);
    reduce_kernel<<<BH, 256>>>();
    pass2_kernel<<<dim3(P2_HALVES, BH), 256>>>(Q, O);
}